// round 12
// baseline (speedup 1.0000x reference)
#include <cuda_runtime.h>
#include <cuda_bf16.h>
#include <cstdint>

#define BB   2
#define KK   32
#define CC   256
#define IHW  512
#define OHW  16
#define NCH  (3 + CC)
#define NPIX (OHW * OHW)

#define MAXSPAN 36          // worst-case window span (aspect extremes -> <=35)
#define SSTRIDE 37          // odd stride -> conflict-free banks
#define TSTRIDE 17          // tmp row stride (16 ox + 1 pad)
#define CHB     2           // channels per staged batch (double-buffered)
#define NBATCH  (16 / CHB)

__device__ __forceinline__ void cp_async4(void* smem_dst, const void* gmem_src) {
    unsigned saddr = (unsigned)__cvta_generic_to_shared(smem_dst);
    asm volatile("cp.async.ca.shared.global [%0], [%1], 4;\n" :: "r"(saddr), "l"(gmem_src));
}
__device__ __forceinline__ void cp_async_commit() {
    asm volatile("cp.async.commit_group;\n" ::: "memory");
}
__device__ __forceinline__ void cp_async_wait_all() {
    asm volatile("cp.async.wait_group 0;\n" ::: "memory");
}

__global__ __launch_bounds__(256, 8)
void roialign_kernel(const float* __restrict__ imgs,
                     const float* __restrict__ bboxess,
                     const int*   __restrict__ counts,
                     const float* __restrict__ p2,
                     const float* __restrict__ p3,
                     const float* __restrict__ p4,
                     const float* __restrict__ p5,
                     float*       __restrict__ out)
{
    const int bk  = blockIdx.x;          // 0..B*K-1
    const int b   = bk / KK;
    const int k   = bk % KK;
    const int grp = blockIdx.y;          // 0 = image channels, 1..16 = feature groups
    const int tid = threadIdx.x;
    const int oy  = tid >> 4;
    const int ox  = tid & 15;

    float* outBox = out + (size_t)bk * NCH * NPIX;

    const bool valid = (k < __ldg(counts + b));
    if (!valid) {
        if (grp == 0) {
            #pragma unroll
            for (int c = 0; c < 3; ++c) outBox[c * NPIX + tid] = 0.0f;
        } else {
            const int c0 = 3 + (grp - 1) * 16;
            #pragma unroll
            for (int cc = 0; cc < 16; ++cc) outBox[(c0 + cc) * NPIX + tid] = 0.0f;
        }
        return;
    }

    // ---- per-box scalars ----
    const float by1 = __ldg(bboxess + bk * 4 + 0);
    const float bx1 = __ldg(bboxess + bk * 4 + 1);
    const float by2 = __ldg(bboxess + bk * 4 + 2);
    const float bx2 = __ldg(bboxess + bk * 4 + 3);

    const float area = (by2 - by1) * (bx2 - bx1);
    float lx = 6.0f + 0.5f * log2f(area * (1.0f / ((float)IHW * (float)IHW)));
    lx = fminf(fmaxf(lx, 2.0f), 5.0f);
    const int lvl = (int)rintf(lx);
    const int ph  = IHW >> lvl;
    const float scale = (float)ph / (float)IHW;

    int y1i = min(max((int)rintf(by1), 0), IHW - 1);
    int x1i = min(max((int)rintf(bx1), 0), IHW - 1);
    int y2i = min(max((int)rintf(by2), y1i + 1), IHW);
    int x2i = min(max((int)rintf(bx2), x1i + 1), IHW);

    // ---- tap tables ----
    __shared__ int   sRowIdx[OHW][4];
    __shared__ float sRowW[OHW][4];
    __shared__ int   sCb[OHW][2];        // clamp-safe column pair base (global)
    __shared__ float sWlo[OHW][2];
    __shared__ float sWhi[OHW][2];
    __shared__ int   sImgY[OHW][2];
    __shared__ float sImgWY[OHW][2];
    __shared__ int   sImgX[OHW][2];
    __shared__ float sImgWX[OHW][2];
    __shared__ int   sRowLo, sRowHi, sColLo, sColHi;
    __shared__ float sWin[2][CHB][MAXSPAN * SSTRIDE];   // ping-pong, 21.3 KB
    __shared__ float sTmp[CHB][MAXSPAN * TSTRIDE];      // 4.9 KB

    if (tid < 16) {
        const int o = tid;
        const float sf = (float)(y2i - y1i);
        const float s  = fmaxf(((float)o + 0.5f) * sf / (float)OHW - 0.5f, 0.0f);
        const int   j0 = (int)floorf(s);
        const int   j1 = min(j0 + 1, (y2i - y1i) - 1);
        const float wt = s - (float)j0;
        const int yi[2]  = { y1i + j0, y1i + j1 };
        const float W[2] = { 1.0f - wt, wt };
        #pragma unroll
        for (int a = 0; a < 2; ++a) {
            sImgY[o][a]  = yi[a];
            sImgWY[o][a] = W[a];
            const float sy = fmaxf(((float)yi[a] + 0.5f) * scale - 0.5f, 0.0f);
            const int   q0 = (int)floorf(sy);
            const int   q1 = min(q0 + 1, ph - 1);
            const float wy = sy - (float)q0;
            sRowIdx[o][2 * a + 0] = q0;
            sRowIdx[o][2 * a + 1] = q1;
            sRowW[o][2 * a + 0] = W[a] * (1.0f - wy);
            sRowW[o][2 * a + 1] = W[a] * wy;
            if (o == 0  && a == 0) sRowLo = q0;
            if (o == 15 && a == 1) sRowHi = q1;
        }
    } else if (tid < 32) {
        const int o = tid - 16;
        const float sf = (float)(x2i - x1i);
        const float s  = fmaxf(((float)o + 0.5f) * sf / (float)OHW - 0.5f, 0.0f);
        const int   j0 = (int)floorf(s);
        const int   j1 = min(j0 + 1, (x2i - x1i) - 1);
        const float wt = s - (float)j0;
        const int xi[2]  = { x1i + j0, x1i + j1 };
        const float W[2] = { 1.0f - wt, wt };
        #pragma unroll
        for (int a = 0; a < 2; ++a) {
            sImgX[o][a]  = xi[a];
            sImgWX[o][a] = W[a];
            const float sx = fmaxf(((float)xi[a] + 0.5f) * scale - 0.5f, 0.0f);
            const int   q0 = (int)floorf(sx);
            const int   q1 = min(q0 + 1, ph - 1);
            const float wx = sx - (float)q0;
            int   cbv;
            float wlo, whi;
            if (q1 > q0) { cbv = q0;     wlo = W[a] * (1.0f - wx); whi = W[a] * wx; }
            else         { cbv = q0 - 1; wlo = 0.0f;               whi = W[a]; }
            sCb[o][a]  = cbv;
            sWlo[o][a] = wlo;
            sWhi[o][a] = whi;
            if (o == 0  && a == 0) sColLo = cbv;
            if (o == 15 && a == 1) sColHi = cbv + 1;
        }
    }
    __syncthreads();

    if (grp == 0) {
        // ---- 3 image channels: 4-tap bilinear on the full-res image ----
        const int   iy0 = sImgY[oy][0], iy1 = sImgY[oy][1];
        const int   ix0 = sImgX[ox][0], ix1 = sImgX[ox][1];
        const float wy0 = sImgWY[oy][0], wy1 = sImgWY[oy][1];
        const float wx0 = sImgWX[ox][0], wx1 = sImgWX[ox][1];
        const float* ib = imgs + (size_t)b * 3 * IHW * IHW;
        #pragma unroll
        for (int c = 0; c < 3; ++c) {
            const float* pc = ib + (size_t)c * IHW * IHW;
            const float v =
                wy0 * (wx0 * __ldg(pc + iy0 * IHW + ix0) + wx1 * __ldg(pc + iy0 * IHW + ix1)) +
                wy1 * (wx0 * __ldg(pc + iy1 * IHW + ix0) + wx1 * __ldg(pc + iy1 * IHW + ix1));
            outBox[c * NPIX + tid] = v;
        }
        return;
    }

    // ---- 16 feature channels: async double-buffered staging + separable contraction ----
    const float* P = (lvl == 2) ? p2 : (lvl == 3) ? p3 : (lvl == 4) ? p4 : p5;
    const int hw = ph * ph;

    const int rowLo = sRowLo;
    const int colLo = sColLo;
    const int rowSpan = min(sRowHi - rowLo + 1, MAXSPAN);
    const int colSpan = min(sColHi - colLo + 1, MAXSPAN);
    const int nWin = rowSpan * colSpan;

    // stage2 row taps (oy-indexed)
    int   rRel[4];
    float rW[4];
    #pragma unroll
    for (int i = 0; i < 4; ++i) {
        rRel[i] = (sRowIdx[oy][i] - rowLo) * TSTRIDE + ox;
        rW[i]   = sRowW[oy][i];
    }
    // stage1 column pairs (ox-indexed)
    const int   cb0 = sCb[ox][0] - colLo, cb1 = sCb[ox][1] - colLo;
    const float wlo0 = sWlo[ox][0], whi0 = sWhi[ox][0];
    const float wlo1 = sWlo[ox][1], whi1 = sWhi[ox][1];

    // stage1 thread mapping: ch = tid>>7 (0..1), rowgroup = (tid>>4)&7, ox = tid&15
    const int s1ch = tid >> 7;
    const int s1rg = (tid >> 4) & 7;

    const int cg0 = (grp - 1) * 16;
    const float* gwin = P + ((size_t)b * CC + cg0) * hw + rowLo * ph + colLo;
    float* outg = outBox + (size_t)(3 + cg0) * NPIX + tid;

    // async staging of one CHB-channel batch into buffer `buf`
    auto stage_async = [&](int buf, int cbatch) {
        const float* gb = gwin + (size_t)cbatch * CHB * hw;
        for (int idx = tid; idx < nWin; idx += 256) {
            const int r = idx / colSpan;
            const int c = idx - r * colSpan;
            const int g = r * ph + c;
            const int s = r * SSTRIDE + c;
            cp_async4(&sWin[buf][0][s], gb + g);
            cp_async4(&sWin[buf][1][s], gb + hw + g);
        }
        cp_async_commit();
    };

    stage_async(0, 0);
    cp_async_wait_all();
    __syncthreads();

    #pragma unroll
    for (int cb = 0; cb < NBATCH; ++cb) {
        const int buf = cb & 1;
        if (cb + 1 < NBATCH) stage_async(buf ^ 1, cb + 1);   // overlaps with stage1/stage2

        // --- stage1: column contraction -> sTmp[ch][r][ox] ---
        {
            const float* wb = sWin[buf][s1ch];
            float* tb = sTmp[s1ch];
            for (int r = s1rg; r < rowSpan; r += 8) {
                const float* wr = wb + r * SSTRIDE;
                float v = wlo0 * wr[cb0];
                v = fmaf(whi0, wr[cb0 + 1], v);
                v = fmaf(wlo1, wr[cb1], v);
                v = fmaf(whi1, wr[cb1 + 1], v);
                tb[r * TSTRIDE + ox] = v;
            }
        }
        __syncthreads();   // sTmp ready

        // --- stage2: row contraction -> output ---
        #pragma unroll
        for (int ch = 0; ch < CHB; ++ch) {
            const float* tb = sTmp[ch];
            float acc = rW[0] * tb[rRel[0]];
            acc = fmaf(rW[1], tb[rRel[1]], acc);
            acc = fmaf(rW[2], tb[rRel[2]], acc);
            acc = fmaf(rW[3], tb[rRel[3]], acc);
            outg[(size_t)(cb * CHB + ch) * NPIX] = acc;
        }

        if (cb + 1 < NBATCH) {
            cp_async_wait_all();   // next batch's copies landed (this thread's groups)
            __syncthreads();       // visible block-wide; also fences sTmp reuse
        }
    }
}

extern "C" void kernel_launch(void* const* d_in, const int* in_sizes, int n_in,
                              void* d_out, int out_size)
{
    const float* imgs    = (const float*)d_in[0];
    const float* bboxess = (const float*)d_in[1];
    const int*   counts  = (const int*)  d_in[2];
    const float* p2      = (const float*)d_in[3];
    const float* p3      = (const float*)d_in[4];
    const float* p4      = (const float*)d_in[5];
    const float* p5      = (const float*)d_in[6];

    dim3 grid(BB * KK, 17);
    roialign_kernel<<<grid, 256>>>(imgs, bboxess, counts, p2, p3, p4, p5,
                                   (float*)d_out);
}

// round 13
// speedup vs baseline: 1.1031x; 1.1031x over previous
#include <cuda_runtime.h>
#include <cuda_bf16.h>
#include <cstdint>

#define BB   2
#define KK   32
#define CC   256
#define IHW  512
#define OHW  16
#define NCH  (3 + CC)
#define NPIX (OHW * OHW)

#define MAXSPAN 36          // worst-case row span (<=35)
#define TSTRIDE 17          // tmp row stride (16 ox + 1 pad)
#define NCHG    16          // feature channels per block

__global__ __launch_bounds__(256, 5)
void roialign_kernel(const float* __restrict__ imgs,
                     const float* __restrict__ bboxess,
                     const int*   __restrict__ counts,
                     const float* __restrict__ p2,
                     const float* __restrict__ p3,
                     const float* __restrict__ p4,
                     const float* __restrict__ p5,
                     float*       __restrict__ out)
{
    const int bk  = blockIdx.x;          // 0..B*K-1
    const int b   = bk / KK;
    const int k   = bk % KK;
    const int grp = blockIdx.y;          // 0 = image channels, 1..16 = feature groups
    const int tid = threadIdx.x;
    const int oy  = tid >> 4;
    const int ox  = tid & 15;

    float* outBox = out + (size_t)bk * NCH * NPIX;

    const bool valid = (k < __ldg(counts + b));
    if (!valid) {
        if (grp == 0) {
            #pragma unroll
            for (int c = 0; c < 3; ++c) outBox[c * NPIX + tid] = 0.0f;
        } else {
            const int c0 = 3 + (grp - 1) * NCHG;
            #pragma unroll
            for (int cc = 0; cc < NCHG; ++cc) outBox[(c0 + cc) * NPIX + tid] = 0.0f;
        }
        return;
    }

    // ---- per-box scalars ----
    const float by1 = __ldg(bboxess + bk * 4 + 0);
    const float bx1 = __ldg(bboxess + bk * 4 + 1);
    const float by2 = __ldg(bboxess + bk * 4 + 2);
    const float bx2 = __ldg(bboxess + bk * 4 + 3);

    const float area = (by2 - by1) * (bx2 - bx1);
    float lx = 6.0f + 0.5f * log2f(area * (1.0f / ((float)IHW * (float)IHW)));
    lx = fminf(fmaxf(lx, 2.0f), 5.0f);
    const int lvl = (int)rintf(lx);
    const int ph  = IHW >> lvl;
    const float scale = (float)ph / (float)IHW;

    int y1i = min(max((int)rintf(by1), 0), IHW - 1);
    int x1i = min(max((int)rintf(bx1), 0), IHW - 1);
    int y2i = min(max((int)rintf(by2), y1i + 1), IHW);
    int x2i = min(max((int)rintf(bx2), x1i + 1), IHW);

    // ---- tap tables ----
    __shared__ int   sRowIdx[OHW][4];    // global feature row per (oy, tap)
    __shared__ float sRowW[OHW][4];
    __shared__ int   sCb[OHW][2];        // clamp-safe GLOBAL column pair base
    __shared__ float sWlo[OHW][2];
    __shared__ float sWhi[OHW][2];
    __shared__ int   sImgY[OHW][2];
    __shared__ float sImgWY[OHW][2];
    __shared__ int   sImgX[OHW][2];
    __shared__ float sImgWX[OHW][2];
    __shared__ int   sRowLo, sRowHi;
    __shared__ float sTmp[NCHG][MAXSPAN * TSTRIDE];   // 39.2 KB column partials

    if (tid < 16) {
        const int o = tid;
        const float sf = (float)(y2i - y1i);
        const float s  = fmaxf(((float)o + 0.5f) * sf / (float)OHW - 0.5f, 0.0f);
        const int   j0 = (int)floorf(s);
        const int   j1 = min(j0 + 1, (y2i - y1i) - 1);
        const float wt = s - (float)j0;
        const int yi[2]  = { y1i + j0, y1i + j1 };
        const float W[2] = { 1.0f - wt, wt };
        #pragma unroll
        for (int a = 0; a < 2; ++a) {
            sImgY[o][a]  = yi[a];
            sImgWY[o][a] = W[a];
            const float sy = fmaxf(((float)yi[a] + 0.5f) * scale - 0.5f, 0.0f);
            const int   q0 = (int)floorf(sy);
            const int   q1 = min(q0 + 1, ph - 1);
            const float wy = sy - (float)q0;
            sRowIdx[o][2 * a + 0] = q0;
            sRowIdx[o][2 * a + 1] = q1;
            sRowW[o][2 * a + 0] = W[a] * (1.0f - wy);
            sRowW[o][2 * a + 1] = W[a] * wy;
            if (o == 0  && a == 0) sRowLo = q0;
            if (o == 15 && a == 1) sRowHi = q1;
        }
    } else if (tid < 32) {
        const int o = tid - 16;
        const float sf = (float)(x2i - x1i);
        const float s  = fmaxf(((float)o + 0.5f) * sf / (float)OHW - 0.5f, 0.0f);
        const int   j0 = (int)floorf(s);
        const int   j1 = min(j0 + 1, (x2i - x1i) - 1);
        const float wt = s - (float)j0;
        const int xi[2]  = { x1i + j0, x1i + j1 };
        const float W[2] = { 1.0f - wt, wt };
        #pragma unroll
        for (int a = 0; a < 2; ++a) {
            sImgX[o][a]  = xi[a];
            sImgWX[o][a] = W[a];
            const float sx = fmaxf(((float)xi[a] + 0.5f) * scale - 0.5f, 0.0f);
            const int   q0 = (int)floorf(sx);
            const int   q1 = min(q0 + 1, ph - 1);
            const float wx = sx - (float)q0;
            // clamp-safe pair: value = wlo*row[cb] + whi*row[cb+1]; cb in [0, ph-2]
            int   cbv;
            float wlo, whi;
            if (q1 > q0) { cbv = q0;     wlo = W[a] * (1.0f - wx); whi = W[a] * wx; }
            else         { cbv = q0 - 1; wlo = 0.0f;               whi = W[a]; }
            sCb[o][a]  = cbv;
            sWlo[o][a] = wlo;
            sWhi[o][a] = whi;
        }
    }
    __syncthreads();

    if (grp == 0) {
        // ---- 3 image channels: 4-tap bilinear on the full-res image ----
        const int   iy0 = sImgY[oy][0], iy1 = sImgY[oy][1];
        const int   ix0 = sImgX[ox][0], ix1 = sImgX[ox][1];
        const float wy0 = sImgWY[oy][0], wy1 = sImgWY[oy][1];
        const float wx0 = sImgWX[ox][0], wx1 = sImgWX[ox][1];
        const float* ib = imgs + (size_t)b * 3 * IHW * IHW;
        #pragma unroll
        for (int c = 0; c < 3; ++c) {
            const float* pc = ib + (size_t)c * IHW * IHW;
            const float v =
                wy0 * (wx0 * __ldg(pc + iy0 * IHW + ix0) + wx1 * __ldg(pc + iy0 * IHW + ix1)) +
                wy1 * (wx0 * __ldg(pc + iy1 * IHW + ix0) + wx1 * __ldg(pc + iy1 * IHW + ix1));
            outBox[c * NPIX + tid] = v;
        }
        return;
    }

    // ---- 16 feature channels: single-phase gmem stage1 -> smem stage2 ----
    const float* P = (lvl == 2) ? p2 : (lvl == 3) ? p3 : (lvl == 4) ? p4 : p5;
    const int hw = ph * ph;

    const int rowLo   = sRowLo;
    const int rowSpan = min(sRowHi - rowLo + 1, MAXSPAN);

    // stage1 column pairs for this thread's ox (global column indices)
    const int   cb0  = sCb[ox][0],  cb1  = sCb[ox][1];
    const float wlo0 = sWlo[ox][0], whi0 = sWhi[ox][0];
    const float wlo1 = sWlo[ox][1], whi1 = sWhi[ox][1];

    // stage2 row taps for this thread's oy
    int   rRel[4];
    float rW[4];
    #pragma unroll
    for (int i = 0; i < 4; ++i) {
        rRel[i] = (sRowIdx[oy][i] - rowLo) * TSTRIDE + ox;
        rW[i]   = sRowW[oy][i];
    }

    const int cg0 = (grp - 1) * NCHG;
    const float* base = P + ((size_t)b * CC + cg0) * hw + (size_t)rowLo * ph;
    float* outg = outBox + (size_t)(3 + cg0) * NPIX + tid;

    // --- stage1: all 16 channels, straight from global memory ---
    // thread handles (r = tid>>4 strided by 16, ox = tid&15) for every channel
    const int r0 = tid >> 4;
    #pragma unroll
    for (int ch = 0; ch < NCHG; ++ch) {
        const float* pc = base + (size_t)ch * hw;
        float* tb = sTmp[ch];
        for (int r = r0; r < rowSpan; r += 16) {
            const float* gr = pc + (size_t)r * ph;
            float v = wlo0 * __ldg(gr + cb0);
            v = fmaf(whi0, __ldg(gr + cb0 + 1), v);
            v = fmaf(wlo1, __ldg(gr + cb1), v);
            v = fmaf(whi1, __ldg(gr + cb1 + 1), v);
            tb[r * TSTRIDE + ox] = v;
        }
    }
    __syncthreads();

    // --- stage2: row contraction -> 16 outputs per thread ---
    #pragma unroll
    for (int ch = 0; ch < NCHG; ++ch) {
        const float* tb = sTmp[ch];
        float acc = rW[0] * tb[rRel[0]];
        acc = fmaf(rW[1], tb[rRel[1]], acc);
        acc = fmaf(rW[2], tb[rRel[2]], acc);
        acc = fmaf(rW[3], tb[rRel[3]], acc);
        outg[(size_t)ch * NPIX] = acc;
    }
}

extern "C" void kernel_launch(void* const* d_in, const int* in_sizes, int n_in,
                              void* d_out, int out_size)
{
    const float* imgs    = (const float*)d_in[0];
    const float* bboxess = (const float*)d_in[1];
    const int*   counts  = (const int*)  d_in[2];
    const float* p2      = (const float*)d_in[3];
    const float* p3      = (const float*)d_in[4];
    const float* p4      = (const float*)d_in[5];
    const float* p5      = (const float*)d_in[6];

    dim3 grid(BB * KK, 17);
    roialign_kernel<<<grid, 256>>>(imgs, bboxess, counts, p2, p3, p4, p5,
                                   (float*)d_out);
}

// round 14
// speedup vs baseline: 1.2136x; 1.1002x over previous
#include <cuda_runtime.h>
#include <cuda_bf16.h>
#include <cstdint>

#define BB   2
#define KK   32
#define CC   256
#define IHW  512
#define OHW  16
#define NCH  (3 + CC)
#define NPIX (OHW * OHW)

#define MAXROWS 38          // worst-case row span (<=37)
#define CAPW    384         // per-channel compact window capacity (analysis: <=~310)
#define TSTRIDE 17          // tmp row stride (16 ox + 1 pad)
#define NCHG    16          // feature channels per block
#define CHB     8           // channels per stage1/stage2 pass

__device__ __forceinline__ void cp_async4(void* smem_dst, const void* gmem_src) {
    unsigned saddr = (unsigned)__cvta_generic_to_shared(smem_dst);
    asm volatile("cp.async.ca.shared.global [%0], [%1], 4;\n" :: "r"(saddr), "l"(gmem_src));
}
__device__ __forceinline__ void cp_async_commit() {
    asm volatile("cp.async.commit_group;\n" ::: "memory");
}
__device__ __forceinline__ void cp_async_wait_all() {
    asm volatile("cp.async.wait_group 0;\n" ::: "memory");
}

__global__ __launch_bounds__(256, 4)
void roialign_kernel(const float* __restrict__ imgs,
                     const float* __restrict__ bboxess,
                     const int*   __restrict__ counts,
                     const float* __restrict__ p2,
                     const float* __restrict__ p3,
                     const float* __restrict__ p4,
                     const float* __restrict__ p5,
                     float*       __restrict__ out)
{
    const int bk  = blockIdx.x;          // 0..B*K-1
    const int b   = bk / KK;
    const int k   = bk % KK;
    const int grp = blockIdx.y;          // 0 = image channels, 1..16 = feature groups
    const int tid = threadIdx.x;
    const int oy  = tid >> 4;
    const int ox  = tid & 15;

    float* outBox = out + (size_t)bk * NCH * NPIX;

    const bool valid = (k < __ldg(counts + b));
    if (!valid) {
        if (grp == 0) {
            #pragma unroll
            for (int c = 0; c < 3; ++c) outBox[c * NPIX + tid] = 0.0f;
        } else {
            const int c0 = 3 + (grp - 1) * NCHG;
            #pragma unroll
            for (int cc = 0; cc < NCHG; ++cc) outBox[(c0 + cc) * NPIX + tid] = 0.0f;
        }
        return;
    }

    // ---- per-box scalars ----
    const float by1 = __ldg(bboxess + bk * 4 + 0);
    const float bx1 = __ldg(bboxess + bk * 4 + 1);
    const float by2 = __ldg(bboxess + bk * 4 + 2);
    const float bx2 = __ldg(bboxess + bk * 4 + 3);

    const float area = (by2 - by1) * (bx2 - bx1);
    float lx = 6.0f + 0.5f * log2f(area * (1.0f / ((float)IHW * (float)IHW)));
    lx = fminf(fmaxf(lx, 2.0f), 5.0f);
    const int lvl = (int)rintf(lx);
    const int ph  = IHW >> lvl;
    const float scale = (float)ph / (float)IHW;

    int y1i = min(max((int)rintf(by1), 0), IHW - 1);
    int x1i = min(max((int)rintf(bx1), 0), IHW - 1);
    int y2i = min(max((int)rintf(by2), y1i + 1), IHW);
    int x2i = min(max((int)rintf(bx2), x1i + 1), IHW);

    // ---- tap tables ----
    __shared__ int   sRowIdx[OHW][4];    // global feature row per (oy, tap)
    __shared__ float sRowW[OHW][4];
    __shared__ int   sCb[OHW][2];        // clamp-safe GLOBAL column pair base
    __shared__ float sWlo[OHW][2];
    __shared__ float sWhi[OHW][2];
    __shared__ int   sImgY[OHW][2];
    __shared__ float sImgWY[OHW][2];
    __shared__ int   sImgX[OHW][2];
    __shared__ float sImgWX[OHW][2];
    __shared__ int   sRowLo, sRowHi, sColLo, sColHi;
    __shared__ float sWin[NCHG][CAPW];           // 24.6 KB compact windows (all 16 ch)
    __shared__ float sTmp[CHB][MAXROWS * TSTRIDE]; // 20.7 KB column partials (8 ch)

    if (tid < 16) {
        const int o = tid;
        const float sf = (float)(y2i - y1i);
        const float s  = fmaxf(((float)o + 0.5f) * sf / (float)OHW - 0.5f, 0.0f);
        const int   j0 = (int)floorf(s);
        const int   j1 = min(j0 + 1, (y2i - y1i) - 1);
        const float wt = s - (float)j0;
        const int yi[2]  = { y1i + j0, y1i + j1 };
        const float W[2] = { 1.0f - wt, wt };
        #pragma unroll
        for (int a = 0; a < 2; ++a) {
            sImgY[o][a]  = yi[a];
            sImgWY[o][a] = W[a];
            const float sy = fmaxf(((float)yi[a] + 0.5f) * scale - 0.5f, 0.0f);
            const int   q0 = (int)floorf(sy);
            const int   q1 = min(q0 + 1, ph - 1);
            const float wy = sy - (float)q0;
            sRowIdx[o][2 * a + 0] = q0;
            sRowIdx[o][2 * a + 1] = q1;
            sRowW[o][2 * a + 0] = W[a] * (1.0f - wy);
            sRowW[o][2 * a + 1] = W[a] * wy;
            if (o == 0  && a == 0) sRowLo = q0;
            if (o == 15 && a == 1) sRowHi = q1;
        }
    } else if (tid < 32) {
        const int o = tid - 16;
        const float sf = (float)(x2i - x1i);
        const float s  = fmaxf(((float)o + 0.5f) * sf / (float)OHW - 0.5f, 0.0f);
        const int   j0 = (int)floorf(s);
        const int   j1 = min(j0 + 1, (x2i - x1i) - 1);
        const float wt = s - (float)j0;
        const int xi[2]  = { x1i + j0, x1i + j1 };
        const float W[2] = { 1.0f - wt, wt };
        #pragma unroll
        for (int a = 0; a < 2; ++a) {
            sImgX[o][a]  = xi[a];
            sImgWX[o][a] = W[a];
            const float sx = fmaxf(((float)xi[a] + 0.5f) * scale - 0.5f, 0.0f);
            const int   q0 = (int)floorf(sx);
            const int   q1 = min(q0 + 1, ph - 1);
            const float wx = sx - (float)q0;
            // clamp-safe pair: value = wlo*row[cb] + whi*row[cb+1]; cb in [0, ph-2]
            int   cbv;
            float wlo, whi;
            if (q1 > q0) { cbv = q0;     wlo = W[a] * (1.0f - wx); whi = W[a] * wx; }
            else         { cbv = q0 - 1; wlo = 0.0f;               whi = W[a]; }
            sCb[o][a]  = cbv;
            sWlo[o][a] = wlo;
            sWhi[o][a] = whi;
            if (o == 0  && a == 0) sColLo = cbv;
            if (o == 15 && a == 1) sColHi = cbv + 1;
        }
    }
    __syncthreads();

    if (grp == 0) {
        // ---- 3 image channels: 4-tap bilinear on the full-res image ----
        const int   iy0 = sImgY[oy][0], iy1 = sImgY[oy][1];
        const int   ix0 = sImgX[ox][0], ix1 = sImgX[ox][1];
        const float wy0 = sImgWY[oy][0], wy1 = sImgWY[oy][1];
        const float wx0 = sImgWX[ox][0], wx1 = sImgWX[ox][1];
        const float* ib = imgs + (size_t)b * 3 * IHW * IHW;
        #pragma unroll
        for (int c = 0; c < 3; ++c) {
            const float* pc = ib + (size_t)c * IHW * IHW;
            const float v =
                wy0 * (wx0 * __ldg(pc + iy0 * IHW + ix0) + wx1 * __ldg(pc + iy0 * IHW + ix1)) +
                wy1 * (wx0 * __ldg(pc + iy1 * IHW + ix0) + wx1 * __ldg(pc + iy1 * IHW + ix1));
            outBox[c * NPIX + tid] = v;
        }
        return;
    }

    // ---- 16 feature channels: single staging burst + two smem contraction passes ----
    const float* P = (lvl == 2) ? p2 : (lvl == 3) ? p3 : (lvl == 4) ? p4 : p5;
    const int hw = ph * ph;

    const int rowLo   = sRowLo;
    const int colLo   = sColLo;
    int rowSpan = min(sRowHi - rowLo + 1, MAXROWS);
    int colSpan = min(sColHi - colLo + 1, MAXROWS);
    const int cstride = colSpan | 1;                       // odd stride
    rowSpan = min(rowSpan, CAPW / cstride);                // defensive; analysis: no-op

    // stage1 column pairs for this thread's ox (window-relative)
    const int   cb0  = sCb[ox][0] - colLo, cb1 = sCb[ox][1] - colLo;
    const float wlo0 = sWlo[ox][0], whi0 = sWhi[ox][0];
    const float wlo1 = sWlo[ox][1], whi1 = sWhi[ox][1];

    // stage2 row taps for this thread's oy
    int   rRel[4];
    float rW[4];
    #pragma unroll
    for (int i = 0; i < 4; ++i) {
        rRel[i] = (sRowIdx[oy][i] - rowLo) * TSTRIDE + ox;
        rW[i]   = sRowW[oy][i];
    }

    const int cg0 = (grp - 1) * NCHG;
    const float* gwin = P + ((size_t)b * CC + cg0) * hw + (size_t)rowLo * ph + colLo;
    float* outg = outBox + (size_t)(3 + cg0) * NPIX + tid;

    const int wid  = tid >> 5;
    const int lane = tid & 31;

    // --- single async staging burst: all 16 channel windows, compact layout ---
    for (int r = wid; r < rowSpan; r += 8) {
        const float* grow = gwin + (size_t)r * ph;
        const int sbase = r * cstride;
        for (int c = lane; c < colSpan; c += 32) {
            #pragma unroll
            for (int ch = 0; ch < NCHG; ++ch)
                cp_async4(&sWin[ch][sbase + c], grow + (size_t)ch * hw + c);
        }
    }
    cp_async_commit();
    cp_async_wait_all();
    __syncthreads();

    // --- two passes of 8 channels: stage1 (LDS gather) -> stage2 (row contraction) ---
    const int rr = tid >> 4;   // 16 row-slots
    #pragma unroll
    for (int pass = 0; pass < NCHG / CHB; ++pass) {
        #pragma unroll
        for (int ch = 0; ch < CHB; ++ch) {
            const float* wb = sWin[pass * CHB + ch];
            float* tb = sTmp[ch];
            for (int r = rr; r < rowSpan; r += 16) {
                const float* wr = wb + r * cstride;
                float v = wlo0 * wr[cb0];
                v = fmaf(whi0, wr[cb0 + 1], v);
                v = fmaf(wlo1, wr[cb1], v);
                v = fmaf(whi1, wr[cb1 + 1], v);
                tb[r * TSTRIDE + ox] = v;
            }
        }
        __syncthreads();   // sTmp ready

        #pragma unroll
        for (int ch = 0; ch < CHB; ++ch) {
            const float* tb = sTmp[ch];
            float acc = rW[0] * tb[rRel[0]];
            acc = fmaf(rW[1], tb[rRel[1]], acc);
            acc = fmaf(rW[2], tb[rRel[2]], acc);
            acc = fmaf(rW[3], tb[rRel[3]], acc);
            outg[(size_t)(pass * CHB + ch) * NPIX] = acc;
        }
        if (pass + 1 < NCHG / CHB) __syncthreads();   // fence sTmp reuse
    }
}

extern "C" void kernel_launch(void* const* d_in, const int* in_sizes, int n_in,
                              void* d_out, int out_size)
{
    const float* imgs    = (const float*)d_in[0];
    const float* bboxess = (const float*)d_in[1];
    const int*   counts  = (const int*)  d_in[2];
    const float* p2      = (const float*)d_in[3];
    const float* p3      = (const float*)d_in[4];
    const float* p4      = (const float*)d_in[5];
    const float* p5      = (const float*)d_in[6];

    dim3 grid(BB * KK, 17);
    roialign_kernel<<<grid, 256>>>(imgs, bboxess, counts, p2, p3, p4, p5,
                                   (float*)d_out);
}